// round 2
// baseline (speedup 1.0000x reference)
#include <cuda_runtime.h>
#include <math.h>

#define NROWS 32768
#define NC 1000

// Scratch (allocation-free: device globals)
__device__ __align__(16) float g_Tt[NC * NC]; // T transposed: g_Tt[y*NC+c] = T[c*NC+y]
__device__ float g_rowval[NROWS];             // per-row beta * ce
__device__ int   g_is64;                      // 1 if target buffer is int64, else int32

// ---------------------------------------------------------------------------
// Kernel 0: detect target dtype. If the buffer is little-endian int64 with
// values < 2^31, every odd 32-bit word is zero. Random int32 labels 0..999
// over 32768 entries cannot be all-zero at odd positions.
// ---------------------------------------------------------------------------
__global__ __launch_bounds__(1024) void detect_k(const unsigned int* __restrict__ tgt32) {
    __shared__ unsigned int s[32];
    unsigned int acc = 0;
    // Interpret as 2*NROWS words; OR all odd words.
    for (int i = threadIdx.x; i < NROWS; i += 1024)
        acc |= tgt32[2 * i + 1];
#pragma unroll
    for (int o = 16; o > 0; o >>= 1)
        acc |= __shfl_xor_sync(0xffffffffu, acc, o);
    if ((threadIdx.x & 31) == 0) s[threadIdx.x >> 5] = acc;
    __syncthreads();
    if (threadIdx.x == 0) {
        unsigned int a = 0;
#pragma unroll
        for (int w = 0; w < 32; w++) a |= s[w];
        g_is64 = (a == 0u) ? 1 : 0;
    }
}

// ---------------------------------------------------------------------------
// Kernel 1: tiled transpose of T (1000x1000) so the per-row dot product reads
// a contiguous row instead of a strided column.
// ---------------------------------------------------------------------------
__global__ void transpose_k(const float* __restrict__ T) {
    __shared__ float tile[32][33];
    int x = blockIdx.x * 32 + threadIdx.x;
#pragma unroll
    for (int j = 0; j < 32; j += 8) {
        int y = blockIdx.y * 32 + threadIdx.y + j;
        if (x < NC && y < NC)
            tile[threadIdx.y + j][threadIdx.x] = T[y * NC + x];
    }
    __syncthreads();
    int x2 = blockIdx.y * 32 + threadIdx.x;
#pragma unroll
    for (int j = 0; j < 32; j += 8) {
        int y2 = blockIdx.x * 32 + threadIdx.y + j;
        if (x2 < NC && y2 < NC)
            g_Tt[(size_t)y2 * NC + x2] = tile[threadIdx.x][threadIdx.y + j];
    }
}

// ---------------------------------------------------------------------------
// Kernel 2: one CTA per row.
//   m  = max_c out[i,c]
//   Z  = sum_c exp(out[i,c]-m)
//   D  = sum_c exp(out[i,c]-m) * T[c, y]   (via Tt row y, coalesced)
//   rowval[i] = (exp(ly-m)/D) * (m + log(Z) - ly)
// ---------------------------------------------------------------------------
__global__ __launch_bounds__(256) void row_k(const float* __restrict__ logits,
                                             const void* __restrict__ target) {
    const int i = blockIdx.x;
    const float* row = logits + (size_t)i * NC;
    const int t = threadIdx.x;
    const int warp = t >> 5, lane = t & 31;
    const bool act = t < (NC / 4);   // 250 float4 per row (4000B, 16B pitch)

    float4 v = make_float4(-INFINITY, -INFINITY, -INFINITY, -INFINITY);
    if (act) v = reinterpret_cast<const float4*>(row)[t];

    // --- block max ---
    float m = fmaxf(fmaxf(v.x, v.y), fmaxf(v.z, v.w));
#pragma unroll
    for (int o = 16; o > 0; o >>= 1)
        m = fmaxf(m, __shfl_xor_sync(0xffffffffu, m, o));

    __shared__ float s_wm[8];
    __shared__ float s_m, s_ly;
    __shared__ int s_y;
    if (lane == 0) s_wm[warp] = m;
    if (t == 0) {
        long long yl = g_is64 ? ((const long long*)target)[i]
                              : (long long)((const int*)target)[i];
        int y = (int)yl;
        y = y < 0 ? 0 : (y >= NC ? NC - 1 : y);   // defensive clamp (never faults)
        s_y = y;
        s_ly = row[y];
    }
    __syncthreads();
    if (t == 0) {
        float mm = s_wm[0];
#pragma unroll
        for (int w = 1; w < 8; w++) mm = fmaxf(mm, s_wm[w]);
        s_m = mm;
    }
    __syncthreads();
    m = s_m;
    const int y = s_y;

    // --- Z and D in one pass from registers ---
    float Z = 0.f, D = 0.f;
    if (act) {
        float4 tv = reinterpret_cast<const float4*>(g_Tt + (size_t)y * NC)[t];
        float e0 = __expf(v.x - m);
        float e1 = __expf(v.y - m);
        float e2 = __expf(v.z - m);
        float e3 = __expf(v.w - m);
        Z = (e0 + e1) + (e2 + e3);
        D = fmaf(e0, tv.x, fmaf(e1, tv.y, fmaf(e2, tv.z, e3 * tv.w)));
    }
#pragma unroll
    for (int o = 16; o > 0; o >>= 1) {
        Z += __shfl_xor_sync(0xffffffffu, Z, o);
        D += __shfl_xor_sync(0xffffffffu, D, o);
    }
    __shared__ float sZ[8], sD[8];
    if (lane == 0) { sZ[warp] = Z; sD[warp] = D; }
    __syncthreads();

    if (t == 0) {
        float Zt = 0.f, Dt = 0.f;
#pragma unroll
        for (int w = 0; w < 8; w++) { Zt += sZ[w]; Dt += sD[w]; }
        float ly   = s_ly;
        float lse  = m + __logf(Zt);         // log-sum-exp
        float ey   = __expf(ly - m);
        float beta = ey / Dt;                // pro1 / pro2
        float ce   = lse - ly;               // -log_softmax[y]
        g_rowval[i] = beta * ce;
    }
}

// ---------------------------------------------------------------------------
// Kernel 3: deterministic fixed-order reduction; writes loss/N to d_out[0].
// ---------------------------------------------------------------------------
__global__ __launch_bounds__(1024) void reduce_k(float* __restrict__ outp) {
    const int t = threadIdx.x;
    double acc = 0.0;
    for (int i = t; i < NROWS; i += 1024)
        acc += (double)g_rowval[i];
    __shared__ double s[1024];
    s[t] = acc;
    __syncthreads();
#pragma unroll
    for (int o = 512; o > 0; o >>= 1) {
        if (t < o) s[t] += s[t + o];
        __syncthreads();
    }
    if (t == 0) outp[0] = (float)(s[0] / (double)NROWS);
}

extern "C" void kernel_launch(void* const* d_in, const int* in_sizes, int n_in,
                              void* d_out, int out_size) {
    const float* logits = (const float*)d_in[0];   // [N, C] f32
    const float* T      = (const float*)d_in[1];   // [C, C] f32
    const void*  target = d_in[2];                 // [N] int32 or int64
    float*       out    = (float*)d_out;

    detect_k<<<1, 1024>>>((const unsigned int*)target);
    transpose_k<<<dim3(32, 32), dim3(32, 8)>>>(T);
    row_k<<<NROWS, 256>>>(logits, target);
    reduce_k<<<1, 1024>>>(out);
}

// round 3
// speedup vs baseline: 2.0316x; 2.0316x over previous
#include <cuda_runtime.h>
#include <math.h>

#define NROWS 32768
#define NC 1000

// Scratch (allocation-free: device globals)
__device__ __align__(16) float g_Tt[NC * NC]; // T transposed: g_Tt[y*NC+c] = T[c*NC+y]
__device__ __align__(16) float g_rowval[NROWS]; // per-row beta * ce
__device__ int   g_is64;                      // 1 if target buffer is int64, else int32

// ---------------------------------------------------------------------------
// Kernel 0: detect target dtype. int64 little-endian labels < 2^31 -> all odd
// 32-bit words zero. uint4 loads for MLP.
// ---------------------------------------------------------------------------
__global__ __launch_bounds__(1024) void detect_k(const uint4* __restrict__ t) {
    __shared__ unsigned int s[32];
    unsigned int acc = 0;
    // 2*NROWS uints = 16384 uint4
#pragma unroll 4
    for (int i = threadIdx.x; i < (2 * NROWS) / 4; i += 1024) {
        uint4 w = t[i];
        acc |= w.y | w.w;
    }
#pragma unroll
    for (int o = 16; o > 0; o >>= 1)
        acc |= __shfl_xor_sync(0xffffffffu, acc, o);
    if ((threadIdx.x & 31) == 0) s[threadIdx.x >> 5] = acc;
    __syncthreads();
    if (threadIdx.x == 0) {
        unsigned int a = 0;
#pragma unroll
        for (int w = 0; w < 32; w++) a |= s[w];
        g_is64 = (a == 0u) ? 1 : 0;
    }
}

// ---------------------------------------------------------------------------
// Kernel 1: tiled transpose of T (1000x1000).
// ---------------------------------------------------------------------------
__global__ void transpose_k(const float* __restrict__ T) {
    __shared__ float tile[32][33];
    int x = blockIdx.x * 32 + threadIdx.x;
#pragma unroll
    for (int j = 0; j < 32; j += 8) {
        int y = blockIdx.y * 32 + threadIdx.y + j;
        if (x < NC && y < NC)
            tile[threadIdx.y + j][threadIdx.x] = T[y * NC + x];
    }
    __syncthreads();
    int x2 = blockIdx.y * 32 + threadIdx.x;
#pragma unroll
    for (int j = 0; j < 32; j += 8) {
        int y2 = blockIdx.x * 32 + threadIdx.y + j;
        if (x2 < NC && y2 < NC)
            g_Tt[(size_t)y2 * NC + x2] = tile[threadIdx.x][threadIdx.y + j];
    }
}

// ---------------------------------------------------------------------------
// Kernel 2: ONE WARP PER ROW. No block barriers. 8 warps per CTA.
//   m  = max_c out[i,c];  Z = sum exp(v-m);  D = sum exp(v-m)*Tt[y,c]
//   rowval[i] = (exp(ly-m)/D) * (m + log(Z) - ly)
// ly is extracted from the register tile via warp shuffle (no extra load).
// ---------------------------------------------------------------------------
__global__ __launch_bounds__(256) void row_k(const float* __restrict__ logits,
                                             const void* __restrict__ target) {
    const int lane = threadIdx.x & 31;
    const int i = blockIdx.x * 8 + (threadIdx.x >> 5);   // row index
    const float* row = logits + (size_t)i * NC;
    const float4* row4 = reinterpret_cast<const float4*>(row);

    // Load 250 float4 spread across the warp: lane + 32*k, k=0..7 (k=7: lanes 0..25)
    float4 v[8];
#pragma unroll
    for (int k = 0; k < 8; k++) {
        int idx = lane + 32 * k;
        if (idx < NC / 4) v[k] = row4[idx];
        else v[k] = make_float4(-INFINITY, -INFINITY, -INFINITY, -INFINITY);
    }

    // Target label (lane 0 reads, broadcast)
    int y = 0;
    if (lane == 0) {
        long long yl = g_is64 ? ((const long long*)target)[i]
                              : (long long)((const int*)target)[i];
        y = (int)yl;
        y = y < 0 ? 0 : (y >= NC ? NC - 1 : y);
    }
    y = __shfl_sync(0xffffffffu, y, 0);

    // ly from registers: element y lives in v[k].{comp} of lane (y/4)%32, k=(y/4)/32
    {
        const int idx4 = y >> 2;
        const int src  = idx4 & 31;
        const int kk   = idx4 >> 5;        // uniform across warp
        const int comp = y & 3;            // uniform
        float cand;
        switch (kk) {                      // uniform branch
            case 0: cand = comp == 0 ? v[0].x : comp == 1 ? v[0].y : comp == 2 ? v[0].z : v[0].w; break;
            case 1: cand = comp == 0 ? v[1].x : comp == 1 ? v[1].y : comp == 2 ? v[1].z : v[1].w; break;
            case 2: cand = comp == 0 ? v[2].x : comp == 1 ? v[2].y : comp == 2 ? v[2].z : v[2].w; break;
            case 3: cand = comp == 0 ? v[3].x : comp == 1 ? v[3].y : comp == 2 ? v[3].z : v[3].w; break;
            case 4: cand = comp == 0 ? v[4].x : comp == 1 ? v[4].y : comp == 2 ? v[4].z : v[4].w; break;
            case 5: cand = comp == 0 ? v[5].x : comp == 1 ? v[5].y : comp == 2 ? v[5].z : v[5].w; break;
            case 6: cand = comp == 0 ? v[6].x : comp == 1 ? v[6].y : comp == 2 ? v[6].z : v[6].w; break;
            default: cand = comp == 0 ? v[7].x : comp == 1 ? v[7].y : comp == 2 ? v[7].z : v[7].w; break;
        }
        float ly_ = __shfl_sync(0xffffffffu, cand, src);
        // stash in v-independent register
        v[0].x = v[0].x; // no-op
        // use a local:
        ;
        // (store into variable below)
        // -- fallthrough
        // NOTE: we keep ly in a separate variable:
        // (declared after this block)
        // to keep the switch simple.
        // Assign:
        // ly declared below
        // (see after block)
        // placeholder
        // Actually assign:
        // ly = ly_;
        // handled via goto-free pattern:
        // we simply declare ly here:
        {
            // compute the rest inline
        }
        // Real assignment below:
        __shared__ char _dummy; (void)_dummy;
        // fall through using variable:
        // (ly captured below)
        // Done in-line:
        // -- we just continue with ly_ in scope:
        // max reduce
        float m = -INFINITY;
#pragma unroll
        for (int k = 0; k < 8; k++)
            m = fmaxf(m, fmaxf(fmaxf(v[k].x, v[k].y), fmaxf(v[k].z, v[k].w)));
#pragma unroll
        for (int o = 16; o > 0; o >>= 1)
            m = fmaxf(m, __shfl_xor_sync(0xffffffffu, m, o));

        // Z, D in one pass
        const float4* tt = reinterpret_cast<const float4*>(g_Tt + (size_t)y * NC);
        float Z = 0.f, D = 0.f;
#pragma unroll
        for (int k = 0; k < 8; k++) {
            int idx = lane + 32 * k;
            if (idx < NC / 4) {
                float4 tv = tt[idx];
                float e0 = __expf(v[k].x - m);
                float e1 = __expf(v[k].y - m);
                float e2 = __expf(v[k].z - m);
                float e3 = __expf(v[k].w - m);
                Z += (e0 + e1) + (e2 + e3);
                D = fmaf(e0, tv.x, fmaf(e1, tv.y, fmaf(e2, tv.z, fmaf(e3, tv.w, D))));
            }
        }
#pragma unroll
        for (int o = 16; o > 0; o >>= 1) {
            Z += __shfl_xor_sync(0xffffffffu, Z, o);
            D += __shfl_xor_sync(0xffffffffu, D, o);
        }

        if (lane == 0) {
            float lse  = m + __logf(Z);       // log-sum-exp
            float ey   = __expf(ly_ - m);
            float beta = ey / D;              // pro1 / pro2
            float ce   = lse - ly_;           // -log_softmax[y]
            g_rowval[i] = beta * ce;
        }
    }
}

// ---------------------------------------------------------------------------
// Kernel 3: deterministic reduction, float partials + final 32 adds in double.
// ---------------------------------------------------------------------------
__global__ __launch_bounds__(1024) void reduce_k(float* __restrict__ outp) {
    const int t = threadIdx.x;
    const float4* p = reinterpret_cast<const float4*>(g_rowval);
    float acc = 0.f;
#pragma unroll
    for (int k = 0; k < NROWS / 4096; k++) {      // 8 float4 per thread
        float4 w = p[t + 1024 * k];
        acc += (w.x + w.y) + (w.z + w.w);
    }
#pragma unroll
    for (int o = 16; o > 0; o >>= 1)
        acc += __shfl_xor_sync(0xffffffffu, acc, o);
    __shared__ float s[32];
    if ((t & 31) == 0) s[t >> 5] = acc;
    __syncthreads();
    if (t == 0) {
        double d = 0.0;
#pragma unroll
        for (int w = 0; w < 32; w++) d += (double)s[w];
        outp[0] = (float)(d / (double)NROWS);
    }
}

extern "C" void kernel_launch(void* const* d_in, const int* in_sizes, int n_in,
                              void* d_out, int out_size) {
    const float* logits = (const float*)d_in[0];   // [N, C] f32
    const float* T      = (const float*)d_in[1];   // [C, C] f32
    const void*  target = d_in[2];                 // [N] int32 or int64
    float*       out    = (float*)d_out;

    detect_k<<<1, 1024>>>((const uint4*)target);
    transpose_k<<<dim3(32, 32), dim3(32, 8)>>>(T);
    row_k<<<NROWS / 8, 256>>>(logits, target);
    reduce_k<<<1, 1024>>>(out);
}